// round 6
// baseline (speedup 1.0000x reference)
#include <cuda_runtime.h>
#include <cuda_bf16.h>
#include <cuda_fp8.h>
#include <cstdint>

// ===========================================================================
// MoE segment-linear, split-precision GEMM:
//   y = x @ Wmix[seg]^T + bias
//   x = xhi + xlo (bf16 split), w = whi + wlo (bf16 split)
//   acc = (xhi*512)*whi [bf16 mma] + fp8(xhi)*fp8(wlo*512) + fp8(xlo*512)*fp8(whi) [e4m3 mma]
//   y = acc/512 + bias   (all products share the 2^9 scale -> one accumulator)
// ===========================================================================

#define MAX_X_ELEMS (16u * 1024u * 1024u)   // N*I
#define MAX_W_ELEMS (16u * 1024u * 1024u)   // B*O*I
#define MAX_TILES 4096
#define MAX_COEFF 512

__device__ __nv_bfloat16 g_xhi[MAX_X_ELEMS];          // bf16(x) * 512
__device__ __nv_bfloat16 g_whi[MAX_W_ELEMS];          // bf16(wmix)
__device__ unsigned char g_x8[2u * MAX_X_ELEMS];      // per 32-chunk: [fp8(xhi) 32B | fp8(xlo*512) 32B]
__device__ unsigned char g_w8[2u * MAX_W_ELEMS];      // per 32-chunk: [fp8(wlo*512) 32B | fp8(whi) 32B]
__device__ int g_tile_row[MAX_TILES];
__device__ int g_tile_rows[MAX_TILES];
__device__ int g_tile_seg[MAX_TILES];
__device__ int g_tile_cnt;

// ---------------------------------------------------------------------------
// Helpers (baseline PTX only)
// ---------------------------------------------------------------------------
__device__ __forceinline__ uint32_t smem_u32(const void* p) {
    uint32_t a;
    asm("{ .reg .u64 t; cvta.to.shared.u64 t, %1; cvt.u32.u64 %0, t; }"
        : "=r"(a) : "l"(p));
    return a;
}
__device__ __forceinline__ void cp16(uint32_t dst, const void* src, int szbytes) {
    asm volatile("cp.async.cg.shared.global [%0], [%1], 16, %2;"
                 :: "r"(dst), "l"(src), "r"(szbytes));
}
#define CP_COMMIT() asm volatile("cp.async.commit_group;")
#define CP_WAIT(n)  asm volatile("cp.async.wait_group %0;" :: "n"(n))

__device__ __forceinline__ void ldm4(uint32_t* r, uint32_t addr) {
    asm volatile("ldmatrix.sync.aligned.m8n8.x4.shared.b16 {%0,%1,%2,%3}, [%4];"
                 : "=r"(r[0]), "=r"(r[1]), "=r"(r[2]), "=r"(r[3]) : "r"(addr));
}
__device__ __forceinline__ void mma_bf16(float* c, const uint32_t* a,
                                         uint32_t b0, uint32_t b1) {
    asm volatile(
        "mma.sync.aligned.m16n8k16.row.col.f32.bf16.bf16.f32 "
        "{%0,%1,%2,%3}, {%4,%5,%6,%7}, {%8,%9}, {%0,%1,%2,%3};"
        : "+f"(c[0]), "+f"(c[1]), "+f"(c[2]), "+f"(c[3])
        : "r"(a[0]), "r"(a[1]), "r"(a[2]), "r"(a[3]), "r"(b0), "r"(b1));
}
__device__ __forceinline__ void mma_fp8(float* c, const uint32_t* a,
                                        uint32_t b0, uint32_t b1) {
    asm volatile(
        "mma.sync.aligned.m16n8k32.row.col.f32.e4m3.e4m3.f32 "
        "{%0,%1,%2,%3}, {%4,%5,%6,%7}, {%8,%9}, {%0,%1,%2,%3};"
        : "+f"(c[0]), "+f"(c[1]), "+f"(c[2]), "+f"(c[3])
        : "r"(a[0]), "r"(a[1]), "r"(a[2]), "r"(a[3]), "r"(b0), "r"(b1));
}

__device__ __forceinline__ uint32_t pack_fp8_4(float a, float b, float c, float d,
                                               float s) {
    uint32_t b0 = (uint32_t)__nv_cvt_float_to_fp8(a * s, __NV_SATFINITE, __NV_E4M3);
    uint32_t b1 = (uint32_t)__nv_cvt_float_to_fp8(b * s, __NV_SATFINITE, __NV_E4M3);
    uint32_t b2 = (uint32_t)__nv_cvt_float_to_fp8(c * s, __NV_SATFINITE, __NV_E4M3);
    uint32_t b3 = (uint32_t)__nv_cvt_float_to_fp8(d * s, __NV_SATFINITE, __NV_E4M3);
    return b0 | (b1 << 8) | (b2 << 16) | (b3 << 24);
}

// ---------------------------------------------------------------------------
// Fused prep kernel.
// ---------------------------------------------------------------------------
#define BMT 128
#define BNT 128
#define BKT 32
#define NSTAGES 3

__global__ void prep_kernel(const float* __restrict__ x,
                            const float* __restrict__ W,
                            const float* __restrict__ coeff,
                            const int* __restrict__ mole_sizes,
                            int E, int B, int I,
                            long long n4, long long OI4, int xb, int wb) {
    int bid = blockIdx.x;
    if (bid < xb) {
        long long idx = (long long)bid * blockDim.x + threadIdx.x;
        if (idx >= n4) return;
        float4 v = reinterpret_cast<const float4*>(x)[idx];
        float h0 = __bfloat162float(__float2bfloat16(v.x));
        float h1 = __bfloat162float(__float2bfloat16(v.y));
        float h2 = __bfloat162float(__float2bfloat16(v.z));
        float h3 = __bfloat162float(__float2bfloat16(v.w));
        __nv_bfloat162* hi2 = reinterpret_cast<__nv_bfloat162*>(g_xhi);
        hi2[idx * 2 + 0] = __halves2bfloat162(__float2bfloat16(h0 * 512.f),
                                              __float2bfloat16(h1 * 512.f));
        hi2[idx * 2 + 1] = __halves2bfloat162(__float2bfloat16(h2 * 512.f),
                                              __float2bfloat16(h3 * 512.f));
        long long e0 = idx * 4;
        long long row = e0 / I;
        int k = (int)(e0 % I);
        long long base = row * (long long)(2 * I) + (k / 32) * 64 + (k % 32);
        uint32_t hw = pack_fp8_4(h0, h1, h2, h3, 1.0f);
        uint32_t lw = pack_fp8_4(v.x - h0, v.y - h1, v.z - h2, v.w - h3, 512.0f);
        *reinterpret_cast<uint32_t*>(g_x8 + base) = hw;
        *reinterpret_cast<uint32_t*>(g_x8 + base + 32) = lw;
        return;
    }
    if (bid < xb + wb) {
        long long idx = (long long)(bid - xb) * blockDim.x + threadIdx.x;
        __shared__ float sc[MAX_COEFF];
        int ncoef = B * E;
        for (int i = threadIdx.x; i < ncoef; i += blockDim.x) sc[i] = coeff[i];
        __syncthreads();
        if (idx >= OI4) return;

        float4 w[8];
#pragma unroll
        for (int e = 0; e < 8; e++) {
            if (e < E)
                w[e] = reinterpret_cast<const float4*>(W)[(long long)e * OI4 + idx];
            else
                w[e] = make_float4(0.f, 0.f, 0.f, 0.f);
        }
        long long OI = OI4 * 4;
        long long e0 = idx * 4;
        long long orow = e0 / I;
        int k = (int)(e0 % I);
        for (int b = 0; b < B; b++) {
            float4 acc = make_float4(0.f, 0.f, 0.f, 0.f);
#pragma unroll
            for (int e = 0; e < 8; e++) {
                if (e < E) {
                    float c = sc[b * E + e];
                    acc.x += c * w[e].x; acc.y += c * w[e].y;
                    acc.z += c * w[e].z; acc.w += c * w[e].w;
                }
            }
            float h0 = __bfloat162float(__float2bfloat16(acc.x));
            float h1 = __bfloat162float(__float2bfloat16(acc.y));
            float h2 = __bfloat162float(__float2bfloat16(acc.z));
            float h3 = __bfloat162float(__float2bfloat16(acc.w));
            __nv_bfloat162* hi2 =
                reinterpret_cast<__nv_bfloat162*>(g_whi + (long long)b * OI);
            hi2[idx * 2 + 0] = __halves2bfloat162(__float2bfloat16(h0),
                                                  __float2bfloat16(h1));
            hi2[idx * 2 + 1] = __halves2bfloat162(__float2bfloat16(h2),
                                                  __float2bfloat16(h3));
            long long base = ((long long)b * OI + orow * I) * 2
                             + (k / 32) * 64 + (k % 32);
            uint32_t lw = pack_fp8_4(acc.x - h0, acc.y - h1,
                                     acc.z - h2, acc.w - h3, 512.0f);
            uint32_t hw = pack_fp8_4(h0, h1, h2, h3, 1.0f);
            *reinterpret_cast<uint32_t*>(g_w8 + base) = lw;       // [wlo*512 | whi]
            *reinterpret_cast<uint32_t*>(g_w8 + base + 32) = hw;
        }
        return;
    }
    // tile table
    if (threadIdx.x == 0) {
        int cnt = 0, off = 0;
        for (int b = 0; b < B; b++) {
            int sz = mole_sizes[b];
            for (int r = 0; r < sz; r += BMT) {
                if (cnt < MAX_TILES) {
                    g_tile_row[cnt] = off + r;
                    g_tile_rows[cnt] = (sz - r) < BMT ? (sz - r) : BMT;
                    g_tile_seg[cnt] = b;
                }
                cnt++;
            }
            off += sz;
        }
        g_tile_cnt = cnt < MAX_TILES ? cnt : MAX_TILES;
    }
}

// ---------------------------------------------------------------------------
// GEMM: 128x128 CTA tile, 3-stage cp.async pipeline, 2 CTAs/SM.
// Per stage (32KB), all tiles 128 rows x 64B, identical swizzle.
// NOTE: fp8 tile row pitch is 2*I BYTES == bf16 pitch (I elems * 2B), and the
// per-chunk K byte offset is c*64 for BOTH formats.
// ---------------------------------------------------------------------------
#define TILE_B   8192
#define STAGE_B  (4 * TILE_B)
#define O_AHI 0
#define O_BHI TILE_B
#define O_A8  (2 * TILE_B)
#define O_B8  (3 * TILE_B)
#define GEMM_SMEM (NSTAGES * STAGE_B)

__device__ __forceinline__ uint32_t swz_off(uint32_t r, uint32_t c) {
    return r * 64u + ((c ^ ((r >> 1) & 3u)) << 4);
}

__device__ __forceinline__ void load_tile(uint32_t sdst, const char* gsrc,
                                          long long pitch, int nvalid, int tid) {
#pragma unroll
    for (int t = 0; t < 2; t++) {
        int idx = tid + t * 256;
        int r = idx >> 2;
        int c = idx & 3;
        uint32_t soff = swz_off((uint32_t)r, (uint32_t)c);
        int rr = r < nvalid ? r : 0;
        int sz = r < nvalid ? 16 : 0;
        cp16(sdst + soff, gsrc + (long long)rr * pitch + c * 16, sz);
    }
}

__global__ __launch_bounds__(256, 2)
void gemm_kernel(const float* __restrict__ bias,
                 float* __restrict__ y,
                 int I, int O) {
    int t = blockIdx.y;
    if (t >= g_tile_cnt) return;

    extern __shared__ __align__(1024) char smem[];
    uint32_t sm0 = smem_u32(smem);

    const int tid = threadIdx.x;
    const int lane = tid & 31;
    const int wid = tid >> 5;
    const int warp_m = wid & 1;
    const int warp_n = wid >> 1;

    const int row0  = g_tile_row[t];
    const int nrows = g_tile_rows[t];
    const int seg   = g_tile_seg[t];
    const int col0  = blockIdx.x * BNT;
    const long long OI = (long long)O * I;
    const long long pitch = (long long)I * 2;  // bytes/row, same for ALL tiles

    const char* whi_base = (const char*)(g_whi + (long long)seg * OI);
    const char* w8_base  = (const char*)(g_w8 + (long long)seg * OI * 2);
    const char* xhi_base = (const char*)g_xhi;
    const char* x8_base  = (const char*)g_x8;

    int ncols = O - col0;
    if (ncols > BNT) ncols = BNT;

    float acc[4][4][4];
#pragma unroll
    for (int mi = 0; mi < 4; mi++)
#pragma unroll
        for (int nj = 0; nj < 4; nj++)
#pragma unroll
            for (int q = 0; q < 4; q++) acc[mi][nj][q] = 0.f;

    const int nch = I / BKT;

#pragma unroll
    for (int s = 0; s < NSTAGES - 1; s++) {
        long long kb = (long long)s * BKT * 2;  // c*64 bytes, both formats
        uint32_t sb = sm0 + s * STAGE_B;
        load_tile(sb + O_AHI, xhi_base + (long long)row0 * pitch + kb, pitch, nrows, tid);
        load_tile(sb + O_BHI, whi_base + (long long)col0 * pitch + kb, pitch, ncols, tid);
        load_tile(sb + O_A8,  x8_base + (long long)row0 * pitch + kb, pitch, nrows, tid);
        load_tile(sb + O_B8,  w8_base + (long long)col0 * pitch + kb, pitch, ncols, tid);
        CP_COMMIT();
    }

    const int rlA  = ((lane >> 3) & 1) * 8 + (lane & 7);
    const int chiA = lane >> 4;
    const int rlB  = ((lane >> 4) & 1) * 8 + (lane & 7);
    const int chiB = (lane >> 3) & 1;

    for (int c = 0; c < nch; c++) {
        CP_WAIT(NSTAGES - 2);
        __syncthreads();

        int pf = c + NSTAGES - 1;
        if (pf < nch) {
            long long kb = (long long)pf * BKT * 2;
            uint32_t sb = sm0 + (pf % NSTAGES) * STAGE_B;
            load_tile(sb + O_AHI, xhi_base + (long long)row0 * pitch + kb, pitch, nrows, tid);
            load_tile(sb + O_BHI, whi_base + (long long)col0 * pitch + kb, pitch, ncols, tid);
            load_tile(sb + O_A8,  x8_base + (long long)row0 * pitch + kb, pitch, nrows, tid);
            load_tile(sb + O_B8,  w8_base + (long long)col0 * pitch + kb, pitch, ncols, tid);
        }
        CP_COMMIT();

        uint32_t sb = sm0 + (c % NSTAGES) * STAGE_B;

        // bf16 hi*hi : 2 k16 steps
#pragma unroll
        for (int ks = 0; ks < 2; ks++) {
            uint32_t ahi[4][4], bh[2][4];
#pragma unroll
            for (int mi = 0; mi < 4; mi++) {
                uint32_t r = (uint32_t)(warp_m * 64 + mi * 16 + rlA);
                ldm4(ahi[mi], sb + O_AHI + swz_off(r, (uint32_t)(ks * 2 + chiA)));
            }
#pragma unroll
            for (int g = 0; g < 2; g++) {
                uint32_t r = (uint32_t)(warp_n * 32 + g * 16 + rlB);
                ldm4(bh[g], sb + O_BHI + swz_off(r, (uint32_t)(ks * 2 + chiB)));
            }
#pragma unroll
            for (int mi = 0; mi < 4; mi++)
#pragma unroll
                for (int nj = 0; nj < 4; nj++) {
                    int g = nj >> 1;
                    int p = (nj & 1) * 2;
                    mma_bf16(acc[mi][nj], ahi[mi], bh[g][p], bh[g][p + 1]);
                }
        }
        // fp8 cross terms: kf=0 -> xhi8 * wlo8,  kf=1 -> xlo8 * whi8  (k32 each)
#pragma unroll
        for (int kf = 0; kf < 2; kf++) {
            uint32_t a8[4][4], b8[2][4];
#pragma unroll
            for (int mi = 0; mi < 4; mi++) {
                uint32_t r = (uint32_t)(warp_m * 64 + mi * 16 + rlA);
                ldm4(a8[mi], sb + O_A8 + swz_off(r, (uint32_t)(kf * 2 + chiA)));
            }
#pragma unroll
            for (int g = 0; g < 2; g++) {
                uint32_t r = (uint32_t)(warp_n * 32 + g * 16 + rlB);
                ldm4(b8[g], sb + O_B8 + swz_off(r, (uint32_t)(kf * 2 + chiB)));
            }
#pragma unroll
            for (int mi = 0; mi < 4; mi++)
#pragma unroll
                for (int nj = 0; nj < 4; nj++) {
                    int g = nj >> 1;
                    int p = (nj & 1) * 2;
                    mma_fp8(acc[mi][nj], a8[mi], b8[g][p], b8[g][p + 1]);
                }
        }
    }

    // epilogue: unscale (1/512), add bias, store
    const float INV = 1.0f / 512.0f;
#pragma unroll
    for (int mi = 0; mi < 4; mi++) {
        int rA = warp_m * 64 + mi * 16 + (lane >> 2);
        int rB = rA + 8;
#pragma unroll
        for (int nj = 0; nj < 4; nj++) {
            int cg = col0 + warp_n * 32 + nj * 8 + (lane & 3) * 2;
            int cl = cg - col0;
            bool c2 = (cl + 2 <= ncols);
            bool c1 = (cl < ncols);
            float b0 = (cg < O) ? bias[cg] : 0.f;
            float b1 = (cg + 1 < O) ? bias[cg + 1] : 0.f;
            if (rA < nrows) {
                long long base = (long long)(row0 + rA) * O + cg;
                if (c2) {
                    float2 v = make_float2(acc[mi][nj][0] * INV + b0,
                                           acc[mi][nj][1] * INV + b1);
                    *reinterpret_cast<float2*>(y + base) = v;
                } else if (c1) {
                    y[base] = acc[mi][nj][0] * INV + b0;
                }
            }
            if (rB < nrows) {
                long long base = (long long)(row0 + rB) * O + cg;
                if (c2) {
                    float2 v = make_float2(acc[mi][nj][2] * INV + b0,
                                           acc[mi][nj][3] * INV + b1);
                    *reinterpret_cast<float2*>(y + base) = v;
                } else if (c1) {
                    y[base] = acc[mi][nj][2] * INV + b0;
                }
            }
        }
    }
}

// ---------------------------------------------------------------------------
// Launch
// ---------------------------------------------------------------------------
extern "C" void kernel_launch(void* const* d_in, const int* in_sizes, int n_in,
                              void* d_out, int out_size) {
    const float* x     = (const float*)d_in[0];   // [N, I]
    const float* W     = (const float*)d_in[1];   // [E, O, I]
    const float* bias  = (const float*)d_in[2];   // [O]
    const float* coeff = (const float*)d_in[3];   // [B, E]
    const int*   msize = (const int*)  d_in[4];   // [B]

    const int O = in_sizes[2];
    const int N = out_size / O;
    const int I = in_sizes[0] / N;
    const int E = in_sizes[1] / (O * I);
    const int B = in_sizes[3] / E;

    // fused prep
    {
        long long n4 = (long long)N * I / 4;
        long long OI4 = (long long)O * I / 4;
        int threads = 256;
        int xb = (int)((n4 + threads - 1) / threads);
        int wb = (int)((OI4 + threads - 1) / threads);
        prep_kernel<<<xb + wb + 1, threads>>>(x, W, coeff, msize,
                                              E, B, I, n4, OI4, xb, wb);
    }

    // GEMM
    {
        static bool attr_set = false;
        if (!attr_set) {
            cudaFuncSetAttribute(gemm_kernel,
                                 cudaFuncAttributeMaxDynamicSharedMemorySize,
                                 GEMM_SMEM);
            attr_set = true;
        }
        int maxTiles = (N + BMT - 1) / BMT + B;
        dim3 grid((O + BNT - 1) / BNT, maxTiles);
        gemm_kernel<<<grid, 256, GEMM_SMEM>>>(bias, (float*)d_out, I, O);
    }
}

// round 7
// speedup vs baseline: 2.5740x; 2.5740x over previous
#include <cuda_runtime.h>
#include <cuda_fp16.h>
#include <cstdint>

// ===========================================================================
// MoE segment-linear via single-term fp16 mma.sync GEMM (fp32 accumulate).
//   y[n,o] = sum_e coeff[seg(n),e] * dot(x[n,:], W[e,o,:]) + bias[o]
// prep: x -> fp16, Wmix[b] = sum_e c[b,e] W[e] -> fp16, tile table
// gemm: y = fp16(x) @ fp16(Wmix[seg])^T + bias   (fp32 accum)
// Error: ~4e-4 norm-relative (fp16 product rounding, independent across K).
// ===========================================================================

#define MAX_X_ELEMS (16u * 1024u * 1024u)   // N*I
#define MAX_W_ELEMS (16u * 1024u * 1024u)   // B*O*I
#define MAX_TILES 4096
#define MAX_COEFF 512

__device__ __half g_xh[MAX_X_ELEMS];
__device__ __half g_wh[MAX_W_ELEMS];
__device__ int g_tile_row[MAX_TILES];
__device__ int g_tile_rows[MAX_TILES];
__device__ int g_tile_seg[MAX_TILES];
__device__ int g_tile_cnt;

// ---------------------------------------------------------------------------
// Helpers (baseline PTX only)
// ---------------------------------------------------------------------------
__device__ __forceinline__ uint32_t smem_u32(const void* p) {
    uint32_t a;
    asm("{ .reg .u64 t; cvta.to.shared.u64 t, %1; cvt.u32.u64 %0, t; }"
        : "=r"(a) : "l"(p));
    return a;
}
__device__ __forceinline__ void cp16(uint32_t dst, const void* src, int szbytes) {
    asm volatile("cp.async.cg.shared.global [%0], [%1], 16, %2;"
                 :: "r"(dst), "l"(src), "r"(szbytes));
}
#define CP_COMMIT() asm volatile("cp.async.commit_group;")
#define CP_WAIT(n)  asm volatile("cp.async.wait_group %0;" :: "n"(n))

__device__ __forceinline__ void ldm4(uint32_t* r, uint32_t addr) {
    asm volatile("ldmatrix.sync.aligned.m8n8.x4.shared.b16 {%0,%1,%2,%3}, [%4];"
                 : "=r"(r[0]), "=r"(r[1]), "=r"(r[2]), "=r"(r[3]) : "r"(addr));
}
__device__ __forceinline__ void mma_f16(float* c, const uint32_t* a,
                                        uint32_t b0, uint32_t b1) {
    asm volatile(
        "mma.sync.aligned.m16n8k16.row.col.f32.f16.f16.f32 "
        "{%0,%1,%2,%3}, {%4,%5,%6,%7}, {%8,%9}, {%0,%1,%2,%3};"
        : "+f"(c[0]), "+f"(c[1]), "+f"(c[2]), "+f"(c[3])
        : "r"(a[0]), "r"(a[1]), "r"(a[2]), "r"(a[3]), "r"(b0), "r"(b1));
}

// ---------------------------------------------------------------------------
// Fused prep kernel.
//   blocks [0, xb)     : x -> fp16
//   blocks [xb, xb+wb) : mix W -> fp16
//   block  xb+wb       : tile table
// ---------------------------------------------------------------------------
#define BMT 128
#define BNT 128
#define BKT 32
#define NSTAGES 4

__global__ void prep_kernel(const float* __restrict__ x,
                            const float* __restrict__ W,
                            const float* __restrict__ coeff,
                            const int* __restrict__ mole_sizes,
                            int E, int B,
                            long long n4, long long OI4, int xb, int wb) {
    int bid = blockIdx.x;
    if (bid < xb) {
        long long idx = (long long)bid * blockDim.x + threadIdx.x;
        if (idx >= n4) return;
        float4 v = reinterpret_cast<const float4*>(x)[idx];
        __half2* h2 = reinterpret_cast<__half2*>(g_xh);
        h2[idx * 2 + 0] = __floats2half2_rn(v.x, v.y);
        h2[idx * 2 + 1] = __floats2half2_rn(v.z, v.w);
        return;
    }
    if (bid < xb + wb) {
        long long idx = (long long)(bid - xb) * blockDim.x + threadIdx.x;
        __shared__ float sc[MAX_COEFF];
        int ncoef = B * E;
        for (int i = threadIdx.x; i < ncoef; i += blockDim.x) sc[i] = coeff[i];
        __syncthreads();
        if (idx >= OI4) return;

        float4 w[8];
#pragma unroll
        for (int e = 0; e < 8; e++) {
            if (e < E)
                w[e] = reinterpret_cast<const float4*>(W)[(long long)e * OI4 + idx];
            else
                w[e] = make_float4(0.f, 0.f, 0.f, 0.f);
        }
        long long OI = OI4 * 4;
        for (int b = 0; b < B; b++) {
            float4 acc = make_float4(0.f, 0.f, 0.f, 0.f);
#pragma unroll
            for (int e = 0; e < 8; e++) {
                if (e < E) {
                    float c = sc[b * E + e];
                    acc.x += c * w[e].x; acc.y += c * w[e].y;
                    acc.z += c * w[e].z; acc.w += c * w[e].w;
                }
            }
            __half2* h2 = reinterpret_cast<__half2*>(g_wh + (long long)b * OI);
            h2[idx * 2 + 0] = __floats2half2_rn(acc.x, acc.y);
            h2[idx * 2 + 1] = __floats2half2_rn(acc.z, acc.w);
        }
        return;
    }
    // tile table
    if (threadIdx.x == 0) {
        int cnt = 0, off = 0;
        for (int b = 0; b < B; b++) {
            int sz = mole_sizes[b];
            for (int r = 0; r < sz; r += BMT) {
                if (cnt < MAX_TILES) {
                    g_tile_row[cnt] = off + r;
                    g_tile_rows[cnt] = (sz - r) < BMT ? (sz - r) : BMT;
                    g_tile_seg[cnt] = b;
                }
                cnt++;
            }
            off += sz;
        }
        g_tile_cnt = cnt < MAX_TILES ? cnt : MAX_TILES;
    }
}

// ---------------------------------------------------------------------------
// GEMM: fp16 mma.sync, 128x128 CTA tile, 4-stage cp.async pipeline, 2 CTAs/SM.
// Per stage (16KB): A tile 8KB | B tile 8KB, 128 rows x 64B, XOR swizzle.
// ---------------------------------------------------------------------------
#define TILE_B   8192
#define STAGE_B  (2 * TILE_B)
#define O_A 0
#define O_B TILE_B
#define GEMM_SMEM (NSTAGES * STAGE_B)

__device__ __forceinline__ uint32_t swz_off(uint32_t r, uint32_t c) {
    return r * 64u + ((c ^ ((r >> 1) & 3u)) << 4);
}

// one tile = 128 rows x 4 x 16B; 512 cp16 per tile; 256 threads -> 2 each
__device__ __forceinline__ void load_tile(uint32_t sdst, const char* gsrc,
                                          long long pitch, int nvalid, int tid) {
#pragma unroll
    for (int t = 0; t < 2; t++) {
        int idx = tid + t * 256;
        int r = idx >> 2;
        int c = idx & 3;
        uint32_t soff = swz_off((uint32_t)r, (uint32_t)c);
        int rr = r < nvalid ? r : 0;
        int sz = r < nvalid ? 16 : 0;
        cp16(sdst + soff, gsrc + (long long)rr * pitch + c * 16, sz);
    }
}

__global__ __launch_bounds__(256, 2)
void gemm_kernel(const float* __restrict__ bias,
                 float* __restrict__ y,
                 int I, int O) {
    int t = blockIdx.y;
    if (t >= g_tile_cnt) return;

    extern __shared__ __align__(1024) char smem[];
    uint32_t sm0 = smem_u32(smem);

    const int tid = threadIdx.x;
    const int lane = tid & 31;
    const int wid = tid >> 5;
    const int warp_m = wid & 1;     // 2 x 64 rows
    const int warp_n = wid >> 1;    // 4 x 32 cols

    const int row0  = g_tile_row[t];
    const int nrows = g_tile_rows[t];
    const int seg   = g_tile_seg[t];
    const int col0  = blockIdx.x * BNT;
    const long long OI = (long long)O * I;
    const long long pitch = (long long)I * 2;   // bytes per row

    const char* wh_base = (const char*)(g_wh + (long long)seg * OI);
    const char* xh_base = (const char*)g_xh;

    int ncols = O - col0;
    if (ncols > BNT) ncols = BNT;

    float acc[4][4][4];
#pragma unroll
    for (int mi = 0; mi < 4; mi++)
#pragma unroll
        for (int nj = 0; nj < 4; nj++)
#pragma unroll
            for (int q = 0; q < 4; q++) acc[mi][nj][q] = 0.f;

    const int nch = I / BKT;

#pragma unroll
    for (int s = 0; s < NSTAGES - 1; s++) {
        long long kb = (long long)s * 64;   // 32 k-elems * 2B
        uint32_t sb = sm0 + s * STAGE_B;
        load_tile(sb + O_A, xh_base + (long long)row0 * pitch + kb, pitch, nrows, tid);
        load_tile(sb + O_B, wh_base + (long long)col0 * pitch + kb, pitch, ncols, tid);
        CP_COMMIT();
    }

    const int rlA  = ((lane >> 3) & 1) * 8 + (lane & 7);
    const int chiA = lane >> 4;
    const int rlB  = ((lane >> 4) & 1) * 8 + (lane & 7);
    const int chiB = (lane >> 3) & 1;

    for (int c = 0; c < nch; c++) {
        CP_WAIT(NSTAGES - 2);
        __syncthreads();

        int pf = c + NSTAGES - 1;
        if (pf < nch) {
            long long kb = (long long)pf * 64;
            uint32_t sb = sm0 + (pf % NSTAGES) * STAGE_B;
            load_tile(sb + O_A, xh_base + (long long)row0 * pitch + kb, pitch, nrows, tid);
            load_tile(sb + O_B, wh_base + (long long)col0 * pitch + kb, pitch, ncols, tid);
        }
        CP_COMMIT();

        uint32_t sb = sm0 + (c % NSTAGES) * STAGE_B;

#pragma unroll
        for (int ks = 0; ks < 2; ks++) {
            uint32_t a[4][4], b[2][4];
#pragma unroll
            for (int mi = 0; mi < 4; mi++) {
                uint32_t r = (uint32_t)(warp_m * 64 + mi * 16 + rlA);
                ldm4(a[mi], sb + O_A + swz_off(r, (uint32_t)(ks * 2 + chiA)));
            }
#pragma unroll
            for (int g = 0; g < 2; g++) {
                uint32_t r = (uint32_t)(warp_n * 32 + g * 16 + rlB);
                ldm4(b[g], sb + O_B + swz_off(r, (uint32_t)(ks * 2 + chiB)));
            }
#pragma unroll
            for (int mi = 0; mi < 4; mi++)
#pragma unroll
                for (int nj = 0; nj < 4; nj++) {
                    int g = nj >> 1;
                    int p = (nj & 1) * 2;
                    mma_f16(acc[mi][nj], a[mi], b[g][p], b[g][p + 1]);
                }
        }
    }

    // epilogue: add bias, store
#pragma unroll
    for (int mi = 0; mi < 4; mi++) {
        int rA = warp_m * 64 + mi * 16 + (lane >> 2);
        int rB = rA + 8;
#pragma unroll
        for (int nj = 0; nj < 4; nj++) {
            int cg = col0 + warp_n * 32 + nj * 8 + (lane & 3) * 2;
            int cl = cg - col0;
            bool c2 = (cl + 2 <= ncols);
            bool c1 = (cl < ncols);
            float b0 = (cg < O) ? bias[cg] : 0.f;
            float b1 = (cg + 1 < O) ? bias[cg + 1] : 0.f;
            if (rA < nrows) {
                long long base = (long long)(row0 + rA) * O + cg;
                if (c2) {
                    float2 v = make_float2(acc[mi][nj][0] + b0,
                                           acc[mi][nj][1] + b1);
                    *reinterpret_cast<float2*>(y + base) = v;
                } else if (c1) {
                    y[base] = acc[mi][nj][0] + b0;
                }
            }
            if (rB < nrows) {
                long long base = (long long)(row0 + rB) * O + cg;
                if (c2) {
                    float2 v = make_float2(acc[mi][nj][2] + b0,
                                           acc[mi][nj][3] + b1);
                    *reinterpret_cast<float2*>(y + base) = v;
                } else if (c1) {
                    y[base] = acc[mi][nj][2] + b0;
                }
            }
        }
    }
}

// ---------------------------------------------------------------------------
// Launch
// ---------------------------------------------------------------------------
extern "C" void kernel_launch(void* const* d_in, const int* in_sizes, int n_in,
                              void* d_out, int out_size) {
    const float* x     = (const float*)d_in[0];   // [N, I]
    const float* W     = (const float*)d_in[1];   // [E, O, I]
    const float* bias  = (const float*)d_in[2];   // [O]
    const float* coeff = (const float*)d_in[3];   // [B, E]
    const int*   msize = (const int*)  d_in[4];   // [B]

    const int O = in_sizes[2];
    const int N = out_size / O;
    const int I = in_sizes[0] / N;
    const int E = in_sizes[1] / (O * I);
    const int B = in_sizes[3] / E;

    // fused prep
    {
        long long n4 = (long long)N * I / 4;
        long long OI4 = (long long)O * I / 4;
        int threads = 256;
        int xb = (int)((n4 + threads - 1) / threads);
        int wb = (int)((OI4 + threads - 1) / threads);
        prep_kernel<<<xb + wb + 1, threads>>>(x, W, coeff, msize,
                                              E, B, n4, OI4, xb, wb);
    }

    // GEMM
    {
        static bool attr_set = false;
        if (!attr_set) {
            cudaFuncSetAttribute(gemm_kernel,
                                 cudaFuncAttributeMaxDynamicSharedMemorySize,
                                 GEMM_SMEM);
            attr_set = true;
        }
        int maxTiles = (N + BMT - 1) / BMT + B;
        dim3 grid((O + BNT - 1) / BNT, maxTiles);
        gemm_kernel<<<grid, 256, GEMM_SMEM>>>(bias, (float*)d_out, I, O);
    }
}

// round 8
// speedup vs baseline: 2.6003x; 1.0102x over previous
#include <cuda_runtime.h>
#include <cuda_fp16.h>
#include <cstdint>

// ===========================================================================
// MoE segment-linear via single-term fp16 mma.sync GEMM (fp32 accumulate).
//   y[n,o] = sum_e coeff[seg(n),e] * dot(x[n,:], W[e,o,:]) + bias[o]
// prep: x -> fp16, Wmix[b] = sum_e c[b,e] W[e] -> fp16, tile table
// gemm: y = fp16(x) @ fp16(Wmix[seg])^T + bias   (fp32 accum)
// R8: BKT 32 -> 64 (half the barriers, longer MMA runs), NSTAGES 4 -> 3.
// ===========================================================================

#define MAX_X_ELEMS (16u * 1024u * 1024u)   // N*I
#define MAX_W_ELEMS (16u * 1024u * 1024u)   // B*O*I
#define MAX_TILES 4096
#define MAX_COEFF 512

__device__ __half g_xh[MAX_X_ELEMS];
__device__ __half g_wh[MAX_W_ELEMS];
__device__ int g_tile_row[MAX_TILES];
__device__ int g_tile_rows[MAX_TILES];
__device__ int g_tile_seg[MAX_TILES];
__device__ int g_tile_cnt;

// ---------------------------------------------------------------------------
// Helpers (baseline PTX only)
// ---------------------------------------------------------------------------
__device__ __forceinline__ uint32_t smem_u32(const void* p) {
    uint32_t a;
    asm("{ .reg .u64 t; cvta.to.shared.u64 t, %1; cvt.u32.u64 %0, t; }"
        : "=r"(a) : "l"(p));
    return a;
}
__device__ __forceinline__ void cp16(uint32_t dst, const void* src, int szbytes) {
    asm volatile("cp.async.cg.shared.global [%0], [%1], 16, %2;"
                 :: "r"(dst), "l"(src), "r"(szbytes));
}
#define CP_COMMIT() asm volatile("cp.async.commit_group;")
#define CP_WAIT(n)  asm volatile("cp.async.wait_group %0;" :: "n"(n))

__device__ __forceinline__ void ldm4(uint32_t* r, uint32_t addr) {
    asm volatile("ldmatrix.sync.aligned.m8n8.x4.shared.b16 {%0,%1,%2,%3}, [%4];"
                 : "=r"(r[0]), "=r"(r[1]), "=r"(r[2]), "=r"(r[3]) : "r"(addr));
}
__device__ __forceinline__ void mma_f16(float* c, const uint32_t* a,
                                        uint32_t b0, uint32_t b1) {
    asm volatile(
        "mma.sync.aligned.m16n8k16.row.col.f32.f16.f16.f32 "
        "{%0,%1,%2,%3}, {%4,%5,%6,%7}, {%8,%9}, {%0,%1,%2,%3};"
        : "+f"(c[0]), "+f"(c[1]), "+f"(c[2]), "+f"(c[3])
        : "r"(a[0]), "r"(a[1]), "r"(a[2]), "r"(a[3]), "r"(b0), "r"(b1));
}

// ---------------------------------------------------------------------------
// Fused prep kernel.
// ---------------------------------------------------------------------------
#define BMT 128
#define BNT 128
#define BKT 64
#define NSTAGES 3

__global__ void prep_kernel(const float* __restrict__ x,
                            const float* __restrict__ W,
                            const float* __restrict__ coeff,
                            const int* __restrict__ mole_sizes,
                            int E, int B,
                            long long n4, long long OI4, int xb, int wb) {
    int bid = blockIdx.x;
    if (bid < xb) {
        long long idx = (long long)bid * blockDim.x + threadIdx.x;
        if (idx >= n4) return;
        float4 v = reinterpret_cast<const float4*>(x)[idx];
        __half2* h2 = reinterpret_cast<__half2*>(g_xh);
        h2[idx * 2 + 0] = __floats2half2_rn(v.x, v.y);
        h2[idx * 2 + 1] = __floats2half2_rn(v.z, v.w);
        return;
    }
    if (bid < xb + wb) {
        long long idx = (long long)(bid - xb) * blockDim.x + threadIdx.x;
        __shared__ float sc[MAX_COEFF];
        int ncoef = B * E;
        for (int i = threadIdx.x; i < ncoef; i += blockDim.x) sc[i] = coeff[i];
        __syncthreads();
        if (idx >= OI4) return;

        float4 w[8];
#pragma unroll
        for (int e = 0; e < 8; e++) {
            if (e < E)
                w[e] = reinterpret_cast<const float4*>(W)[(long long)e * OI4 + idx];
            else
                w[e] = make_float4(0.f, 0.f, 0.f, 0.f);
        }
        long long OI = OI4 * 4;
        for (int b = 0; b < B; b++) {
            float4 acc = make_float4(0.f, 0.f, 0.f, 0.f);
#pragma unroll
            for (int e = 0; e < 8; e++) {
                if (e < E) {
                    float c = sc[b * E + e];
                    acc.x += c * w[e].x; acc.y += c * w[e].y;
                    acc.z += c * w[e].z; acc.w += c * w[e].w;
                }
            }
            __half2* h2 = reinterpret_cast<__half2*>(g_wh + (long long)b * OI);
            h2[idx * 2 + 0] = __floats2half2_rn(acc.x, acc.y);
            h2[idx * 2 + 1] = __floats2half2_rn(acc.z, acc.w);
        }
        return;
    }
    // tile table
    if (threadIdx.x == 0) {
        int cnt = 0, off = 0;
        for (int b = 0; b < B; b++) {
            int sz = mole_sizes[b];
            for (int r = 0; r < sz; r += BMT) {
                if (cnt < MAX_TILES) {
                    g_tile_row[cnt] = off + r;
                    g_tile_rows[cnt] = (sz - r) < BMT ? (sz - r) : BMT;
                    g_tile_seg[cnt] = b;
                }
                cnt++;
            }
            off += sz;
        }
        g_tile_cnt = cnt < MAX_TILES ? cnt : MAX_TILES;
    }
}

// ---------------------------------------------------------------------------
// GEMM: fp16 mma.sync, 128x128 CTA tile, BKT=64, 3-stage pipeline, 2 CTAs/SM.
// Per stage (32KB): A 16KB | B 16KB. Tile = 128 rows x 128B (8 x 16B chunks).
// Swizzle: chunk' = c ^ (r & 7)  -> conflict-free STS (8-lane groups cover all
// 8 chunks of one row) and ldmatrix (8 consecutive rows hit 8 distinct chunks).
// ---------------------------------------------------------------------------
#define TILE_B   16384
#define STAGE_B  (2 * TILE_B)
#define O_A 0
#define O_B TILE_B
#define GEMM_SMEM (NSTAGES * STAGE_B)

__device__ __forceinline__ uint32_t swz8(uint32_t r, uint32_t c) {
    return r * 128u + ((c ^ (r & 7u)) << 4);
}

// one tile = 128 rows x 8 x 16B = 1024 cp16; 256 threads -> 4 each
__device__ __forceinline__ void load_tile(uint32_t sdst, const char* gsrc,
                                          long long pitch, int nvalid, int tid) {
#pragma unroll
    for (int t = 0; t < 4; t++) {
        int idx = tid + t * 256;
        int r = idx >> 3;
        int c = idx & 7;
        uint32_t soff = swz8((uint32_t)r, (uint32_t)c);
        int rr = r < nvalid ? r : 0;
        int sz = r < nvalid ? 16 : 0;
        cp16(sdst + soff, gsrc + (long long)rr * pitch + c * 16, sz);
    }
}

__global__ __launch_bounds__(256, 2)
void gemm_kernel(const float* __restrict__ bias,
                 float* __restrict__ y,
                 int I, int O) {
    int t = blockIdx.y;
    if (t >= g_tile_cnt) return;

    extern __shared__ __align__(1024) char smem[];
    uint32_t sm0 = smem_u32(smem);

    const int tid = threadIdx.x;
    const int lane = tid & 31;
    const int wid = tid >> 5;
    const int warp_m = wid & 1;     // 2 x 64 rows
    const int warp_n = wid >> 1;    // 4 x 32 cols

    const int row0  = g_tile_row[t];
    const int nrows = g_tile_rows[t];
    const int seg   = g_tile_seg[t];
    const int col0  = blockIdx.x * BNT;
    const long long OI = (long long)O * I;
    const long long pitch = (long long)I * 2;   // bytes per row

    const char* wh_base = (const char*)(g_wh + (long long)seg * OI);
    const char* xh_base = (const char*)g_xh;

    int ncols = O - col0;
    if (ncols > BNT) ncols = BNT;

    float acc[4][4][4];
#pragma unroll
    for (int mi = 0; mi < 4; mi++)
#pragma unroll
        for (int nj = 0; nj < 4; nj++)
#pragma unroll
            for (int q = 0; q < 4; q++) acc[mi][nj][q] = 0.f;

    const int nch = I / BKT;   // 16

#pragma unroll
    for (int s = 0; s < NSTAGES - 1; s++) {
        long long kb = (long long)s * 128;  // 64 k-elems * 2B
        uint32_t sb = sm0 + s * STAGE_B;
        load_tile(sb + O_A, xh_base + (long long)row0 * pitch + kb, pitch, nrows, tid);
        load_tile(sb + O_B, wh_base + (long long)col0 * pitch + kb, pitch, ncols, tid);
        CP_COMMIT();
    }

    const int rlA  = ((lane >> 3) & 1) * 8 + (lane & 7);
    const int chiA = lane >> 4;
    const int rlB  = ((lane >> 4) & 1) * 8 + (lane & 7);
    const int chiB = (lane >> 3) & 1;

    for (int c = 0; c < nch; c++) {
        CP_WAIT(NSTAGES - 2);
        __syncthreads();

        int pf = c + NSTAGES - 1;
        if (pf < nch) {
            long long kb = (long long)pf * 128;
            uint32_t sb = sm0 + (pf % NSTAGES) * STAGE_B;
            load_tile(sb + O_A, xh_base + (long long)row0 * pitch + kb, pitch, nrows, tid);
            load_tile(sb + O_B, wh_base + (long long)col0 * pitch + kb, pitch, ncols, tid);
        }
        CP_COMMIT();

        uint32_t sb = sm0 + (c % NSTAGES) * STAGE_B;

#pragma unroll
        for (int ks = 0; ks < 4; ks++) {       // 4 x k16 per 64-chunk
            uint32_t a[4][4], b[2][4];
#pragma unroll
            for (int mi = 0; mi < 4; mi++) {
                uint32_t r = (uint32_t)(warp_m * 64 + mi * 16 + rlA);
                ldm4(a[mi], sb + O_A + swz8(r, (uint32_t)(ks * 2 + chiA)));
            }
#pragma unroll
            for (int g = 0; g < 2; g++) {
                uint32_t r = (uint32_t)(warp_n * 32 + g * 16 + rlB);
                ldm4(b[g], sb + O_B + swz8(r, (uint32_t)(ks * 2 + chiB)));
            }
#pragma unroll
            for (int mi = 0; mi < 4; mi++)
#pragma unroll
                for (int nj = 0; nj < 4; nj++) {
                    int g = nj >> 1;
                    int p = (nj & 1) * 2;
                    mma_f16(acc[mi][nj], a[mi], b[g][p], b[g][p + 1]);
                }
        }
    }

    // epilogue: add bias, store
#pragma unroll
    for (int mi = 0; mi < 4; mi++) {
        int rA = warp_m * 64 + mi * 16 + (lane >> 2);
        int rB = rA + 8;
#pragma unroll
        for (int nj = 0; nj < 4; nj++) {
            int cg = col0 + warp_n * 32 + nj * 8 + (lane & 3) * 2;
            int cl = cg - col0;
            bool c2 = (cl + 2 <= ncols);
            bool c1 = (cl < ncols);
            float b0 = (cg < O) ? bias[cg] : 0.f;
            float b1 = (cg + 1 < O) ? bias[cg + 1] : 0.f;
            if (rA < nrows) {
                long long base = (long long)(row0 + rA) * O + cg;
                if (c2) {
                    float2 v = make_float2(acc[mi][nj][0] + b0,
                                           acc[mi][nj][1] + b1);
                    *reinterpret_cast<float2*>(y + base) = v;
                } else if (c1) {
                    y[base] = acc[mi][nj][0] + b0;
                }
            }
            if (rB < nrows) {
                long long base = (long long)(row0 + rB) * O + cg;
                if (c2) {
                    float2 v = make_float2(acc[mi][nj][2] + b0,
                                           acc[mi][nj][3] + b1);
                    *reinterpret_cast<float2*>(y + base) = v;
                } else if (c1) {
                    y[base] = acc[mi][nj][2] + b0;
                }
            }
        }
    }
}

// ---------------------------------------------------------------------------
// Launch
// ---------------------------------------------------------------------------
extern "C" void kernel_launch(void* const* d_in, const int* in_sizes, int n_in,
                              void* d_out, int out_size) {
    const float* x     = (const float*)d_in[0];   // [N, I]
    const float* W     = (const float*)d_in[1];   // [E, O, I]
    const float* bias  = (const float*)d_in[2];   // [O]
    const float* coeff = (const float*)d_in[3];   // [B, E]
    const int*   msize = (const int*)  d_in[4];   // [B]

    const int O = in_sizes[2];
    const int N = out_size / O;
    const int I = in_sizes[0] / N;
    const int E = in_sizes[1] / (O * I);
    const int B = in_sizes[3] / E;

    // fused prep
    {
        long long n4 = (long long)N * I / 4;
        long long OI4 = (long long)O * I / 4;
        int threads = 256;
        int xb = (int)((n4 + threads - 1) / threads);
        int wb = (int)((OI4 + threads - 1) / threads);
        prep_kernel<<<xb + wb + 1, threads>>>(x, W, coeff, msize,
                                              E, B, n4, OI4, xb, wb);
    }

    // GEMM
    {
        static bool attr_set = false;
        if (!attr_set) {
            cudaFuncSetAttribute(gemm_kernel,
                                 cudaFuncAttributeMaxDynamicSharedMemorySize,
                                 GEMM_SMEM);
            attr_set = true;
        }
        int maxTiles = (N + BMT - 1) / BMT + B;
        dim3 grid((O + BNT - 1) / BNT, maxTiles);
        gemm_kernel<<<grid, 256, GEMM_SMEM>>>(bias, (float*)d_out, I, O);
    }
}

// round 9
// speedup vs baseline: 2.6506x; 1.0193x over previous
#include <cuda_runtime.h>
#include <cuda_fp16.h>
#include <cstdint>

// ===========================================================================
// MoE segment-linear via single-term fp16 mma.sync GEMM (fp32 accumulate).
//   y[n,o] = sum_e coeff[seg(n),e] * dot(x[n,:], W[e,o,:]) + bias[o]
// R9: 4 warps/CTA, 64x64 warp tile (was 8 warps, 64x32) -> smem bytes per MMA
// 192 -> 128, cutting LDSM/L1 pressure which co-bound the tensor pipe.
// ===========================================================================

#define MAX_X_ELEMS (16u * 1024u * 1024u)   // N*I
#define MAX_W_ELEMS (16u * 1024u * 1024u)   // B*O*I
#define MAX_TILES 4096
#define MAX_COEFF 512

__device__ __half g_xh[MAX_X_ELEMS];
__device__ __half g_wh[MAX_W_ELEMS];
__device__ int g_tile_row[MAX_TILES];
__device__ int g_tile_rows[MAX_TILES];
__device__ int g_tile_seg[MAX_TILES];
__device__ int g_tile_cnt;

// ---------------------------------------------------------------------------
// Helpers (baseline PTX only)
// ---------------------------------------------------------------------------
__device__ __forceinline__ uint32_t smem_u32(const void* p) {
    uint32_t a;
    asm("{ .reg .u64 t; cvta.to.shared.u64 t, %1; cvt.u32.u64 %0, t; }"
        : "=r"(a) : "l"(p));
    return a;
}
__device__ __forceinline__ void cp16(uint32_t dst, const void* src, int szbytes) {
    asm volatile("cp.async.cg.shared.global [%0], [%1], 16, %2;"
                 :: "r"(dst), "l"(src), "r"(szbytes));
}
#define CP_COMMIT() asm volatile("cp.async.commit_group;")
#define CP_WAIT(n)  asm volatile("cp.async.wait_group %0;" :: "n"(n))

__device__ __forceinline__ void ldm4(uint32_t* r, uint32_t addr) {
    asm volatile("ldmatrix.sync.aligned.m8n8.x4.shared.b16 {%0,%1,%2,%3}, [%4];"
                 : "=r"(r[0]), "=r"(r[1]), "=r"(r[2]), "=r"(r[3]) : "r"(addr));
}
__device__ __forceinline__ void mma_f16(float* c, const uint32_t* a,
                                        uint32_t b0, uint32_t b1) {
    asm volatile(
        "mma.sync.aligned.m16n8k16.row.col.f32.f16.f16.f32 "
        "{%0,%1,%2,%3}, {%4,%5,%6,%7}, {%8,%9}, {%0,%1,%2,%3};"
        : "+f"(c[0]), "+f"(c[1]), "+f"(c[2]), "+f"(c[3])
        : "r"(a[0]), "r"(a[1]), "r"(a[2]), "r"(a[3]), "r"(b0), "r"(b1));
}

// ---------------------------------------------------------------------------
// Fused prep kernel (unchanged from R8).
// ---------------------------------------------------------------------------
#define BMT 128
#define BNT 128
#define BKT 64
#define NSTAGES 3

__global__ void prep_kernel(const float* __restrict__ x,
                            const float* __restrict__ W,
                            const float* __restrict__ coeff,
                            const int* __restrict__ mole_sizes,
                            int E, int B,
                            long long n4, long long OI4, int xb, int wb) {
    int bid = blockIdx.x;
    if (bid < xb) {
        long long idx = (long long)bid * blockDim.x + threadIdx.x;
        if (idx >= n4) return;
        float4 v = reinterpret_cast<const float4*>(x)[idx];
        __half2* h2 = reinterpret_cast<__half2*>(g_xh);
        h2[idx * 2 + 0] = __floats2half2_rn(v.x, v.y);
        h2[idx * 2 + 1] = __floats2half2_rn(v.z, v.w);
        return;
    }
    if (bid < xb + wb) {
        long long idx = (long long)(bid - xb) * blockDim.x + threadIdx.x;
        __shared__ float sc[MAX_COEFF];
        int ncoef = B * E;
        for (int i = threadIdx.x; i < ncoef; i += blockDim.x) sc[i] = coeff[i];
        __syncthreads();
        if (idx >= OI4) return;

        float4 w[8];
#pragma unroll
        for (int e = 0; e < 8; e++) {
            if (e < E)
                w[e] = reinterpret_cast<const float4*>(W)[(long long)e * OI4 + idx];
            else
                w[e] = make_float4(0.f, 0.f, 0.f, 0.f);
        }
        long long OI = OI4 * 4;
        for (int b = 0; b < B; b++) {
            float4 acc = make_float4(0.f, 0.f, 0.f, 0.f);
#pragma unroll
            for (int e = 0; e < 8; e++) {
                if (e < E) {
                    float c = sc[b * E + e];
                    acc.x += c * w[e].x; acc.y += c * w[e].y;
                    acc.z += c * w[e].z; acc.w += c * w[e].w;
                }
            }
            __half2* h2 = reinterpret_cast<__half2*>(g_wh + (long long)b * OI);
            h2[idx * 2 + 0] = __floats2half2_rn(acc.x, acc.y);
            h2[idx * 2 + 1] = __floats2half2_rn(acc.z, acc.w);
        }
        return;
    }
    // tile table
    if (threadIdx.x == 0) {
        int cnt = 0, off = 0;
        for (int b = 0; b < B; b++) {
            int sz = mole_sizes[b];
            for (int r = 0; r < sz; r += BMT) {
                if (cnt < MAX_TILES) {
                    g_tile_row[cnt] = off + r;
                    g_tile_rows[cnt] = (sz - r) < BMT ? (sz - r) : BMT;
                    g_tile_seg[cnt] = b;
                }
                cnt++;
            }
            off += sz;
        }
        g_tile_cnt = cnt < MAX_TILES ? cnt : MAX_TILES;
    }
}

// ---------------------------------------------------------------------------
// GEMM: fp16 mma.sync, 128x128 CTA tile, BKT=64, 3-stage pipeline, 2 CTAs/SM.
// 128 threads (4 warps, 2x2 grid), warp tile 64x64, acc = 128 fp32 regs/thread.
// Per stage (32KB): A 16KB | B 16KB. Tile = 128 rows x 128B (8 x 16B chunks).
// Swizzle: chunk' = c ^ (r & 7).
// ---------------------------------------------------------------------------
#define TILE_B   16384
#define STAGE_B  (2 * TILE_B)
#define O_A 0
#define O_B TILE_B
#define GEMM_SMEM (NSTAGES * STAGE_B)
#define GTHREADS 128

__device__ __forceinline__ uint32_t swz8(uint32_t r, uint32_t c) {
    return r * 128u + ((c ^ (r & 7u)) << 4);
}

// one tile = 128 rows x 8 x 16B = 1024 cp16; 128 threads -> 8 each
__device__ __forceinline__ void load_tile(uint32_t sdst, const char* gsrc,
                                          long long pitch, int nvalid, int tid) {
#pragma unroll
    for (int t = 0; t < 8; t++) {
        int idx = tid + t * GTHREADS;
        int r = idx >> 3;
        int c = idx & 7;
        uint32_t soff = swz8((uint32_t)r, (uint32_t)c);
        int rr = r < nvalid ? r : 0;
        int sz = r < nvalid ? 16 : 0;
        cp16(sdst + soff, gsrc + (long long)rr * pitch + c * 16, sz);
    }
}

__global__ __launch_bounds__(GTHREADS, 2)
void gemm_kernel(const float* __restrict__ bias,
                 float* __restrict__ y,
                 int I, int O) {
    int t = blockIdx.y;
    if (t >= g_tile_cnt) return;

    extern __shared__ __align__(1024) char smem[];
    uint32_t sm0 = smem_u32(smem);

    const int tid = threadIdx.x;
    const int lane = tid & 31;
    const int wid = tid >> 5;
    const int warp_m = wid & 1;     // 2 x 64 rows
    const int warp_n = wid >> 1;    // 2 x 64 cols

    const int row0  = g_tile_row[t];
    const int nrows = g_tile_rows[t];
    const int seg   = g_tile_seg[t];
    const int col0  = blockIdx.x * BNT;
    const long long OI = (long long)O * I;
    const long long pitch = (long long)I * 2;   // bytes per row

    const char* wh_base = (const char*)(g_wh + (long long)seg * OI);
    const char* xh_base = (const char*)g_xh;

    int ncols = O - col0;
    if (ncols > BNT) ncols = BNT;

    float acc[4][8][4];
#pragma unroll
    for (int mi = 0; mi < 4; mi++)
#pragma unroll
        for (int nj = 0; nj < 8; nj++)
#pragma unroll
            for (int q = 0; q < 4; q++) acc[mi][nj][q] = 0.f;

    const int nch = I / BKT;   // 16

#pragma unroll
    for (int s = 0; s < NSTAGES - 1; s++) {
        long long kb = (long long)s * 128;  // 64 k-elems * 2B
        uint32_t sb = sm0 + s * STAGE_B;
        load_tile(sb + O_A, xh_base + (long long)row0 * pitch + kb, pitch, nrows, tid);
        load_tile(sb + O_B, wh_base + (long long)col0 * pitch + kb, pitch, ncols, tid);
        CP_COMMIT();
    }

    const int rlA  = ((lane >> 3) & 1) * 8 + (lane & 7);
    const int chiA = lane >> 4;
    const int rlB  = ((lane >> 4) & 1) * 8 + (lane & 7);
    const int chiB = (lane >> 3) & 1;

    for (int c = 0; c < nch; c++) {
        CP_WAIT(NSTAGES - 2);
        __syncthreads();

        int pf = c + NSTAGES - 1;
        if (pf < nch) {
            long long kb = (long long)pf * 128;
            uint32_t sb = sm0 + (pf % NSTAGES) * STAGE_B;
            load_tile(sb + O_A, xh_base + (long long)row0 * pitch + kb, pitch, nrows, tid);
            load_tile(sb + O_B, wh_base + (long long)col0 * pitch + kb, pitch, ncols, tid);
        }
        CP_COMMIT();

        uint32_t sb = sm0 + (c % NSTAGES) * STAGE_B;

#pragma unroll
        for (int ks = 0; ks < 4; ks++) {       // 4 x k16 per 64-chunk
            uint32_t a[4][4], b[4][4];
#pragma unroll
            for (int mi = 0; mi < 4; mi++) {
                uint32_t r = (uint32_t)(warp_m * 64 + mi * 16 + rlA);
                ldm4(a[mi], sb + O_A + swz8(r, (uint32_t)(ks * 2 + chiA)));
            }
#pragma unroll
            for (int g = 0; g < 4; g++) {
                uint32_t r = (uint32_t)(warp_n * 64 + g * 16 + rlB);
                ldm4(b[g], sb + O_B + swz8(r, (uint32_t)(ks * 2 + chiB)));
            }
#pragma unroll
            for (int mi = 0; mi < 4; mi++)
#pragma unroll
                for (int nj = 0; nj < 8; nj++) {
                    int g = nj >> 1;
                    int p = (nj & 1) * 2;
                    mma_f16(acc[mi][nj], a[mi], b[g][p], b[g][p + 1]);
                }
        }
    }

    // epilogue: add bias, store
#pragma unroll
    for (int mi = 0; mi < 4; mi++) {
        int rA = warp_m * 64 + mi * 16 + (lane >> 2);
        int rB = rA + 8;
#pragma unroll
        for (int nj = 0; nj < 8; nj++) {
            int cg = col0 + warp_n * 64 + nj * 8 + (lane & 3) * 2;
            int cl = cg - col0;
            bool c2 = (cl + 2 <= ncols);
            bool c1 = (cl < ncols);
            float b0 = (cg < O) ? bias[cg] : 0.f;
            float b1 = (cg + 1 < O) ? bias[cg + 1] : 0.f;
            if (rA < nrows) {
                long long base = (long long)(row0 + rA) * O + cg;
                if (c2) {
                    float2 v = make_float2(acc[mi][nj][0] + b0,
                                           acc[mi][nj][1] + b1);
                    *reinterpret_cast<float2*>(y + base) = v;
                } else if (c1) {
                    y[base] = acc[mi][nj][0] + b0;
                }
            }
            if (rB < nrows) {
                long long base = (long long)(row0 + rB) * O + cg;
                if (c2) {
                    float2 v = make_float2(acc[mi][nj][2] + b0,
                                           acc[mi][nj][3] + b1);
                    *reinterpret_cast<float2*>(y + base) = v;
                } else if (c1) {
                    y[base] = acc[mi][nj][2] + b0;
                }
            }
        }
    }
}

// ---------------------------------------------------------------------------
// Launch
// ---------------------------------------------------------------------------
extern "C" void kernel_launch(void* const* d_in, const int* in_sizes, int n_in,
                              void* d_out, int out_size) {
    const float* x     = (const float*)d_in[0];   // [N, I]
    const float* W     = (const float*)d_in[1];   // [E, O, I]
    const float* bias  = (const float*)d_in[2];   // [O]
    const float* coeff = (const float*)d_in[3];   // [B, E]
    const int*   msize = (const int*)  d_in[4];   // [B]

    const int O = in_sizes[2];
    const int N = out_size / O;
    const int I = in_sizes[0] / N;
    const int E = in_sizes[1] / (O * I);
    const int B = in_sizes[3] / E;

    // fused prep
    {
        long long n4 = (long long)N * I / 4;
        long long OI4 = (long long)O * I / 4;
        int threads = 256;
        int xb = (int)((n4 + threads - 1) / threads);
        int wb = (int)((OI4 + threads - 1) / threads);
        prep_kernel<<<xb + wb + 1, threads>>>(x, W, coeff, msize,
                                              E, B, n4, OI4, xb, wb);
    }

    // GEMM
    {
        static bool attr_set = false;
        if (!attr_set) {
            cudaFuncSetAttribute(gemm_kernel,
                                 cudaFuncAttributeMaxDynamicSharedMemorySize,
                                 GEMM_SMEM);
            attr_set = true;
        }
        int maxTiles = (N + BMT - 1) / BMT + B;
        dim3 grid((O + BNT - 1) / BNT, maxTiles);
        gemm_kernel<<<grid, GTHREADS, GEMM_SMEM>>>(bias, (float*)d_out, I, O);
    }
}